// round 6
// baseline (speedup 1.0000x reference)
#include <cuda_runtime.h>

#define NN   1024
#define BB   32
#define NBIN 1024

#define FPSCALE   0x1p40f
#define FPISCALE  0x1p-40f

__device__ __forceinline__ long long fpenc(float v) { return (long long)(v * FPSCALE); }
__device__ __forceinline__ float     fpdec(long long u) { return __ll2float_rn(u) * FPISCALE; }

__device__ __forceinline__ int IDX(int i) { return i + (i >> 5); }
#define PADN (NN + (NN >> 5))   // 1056

// shared layout (bytes):
//   tab  : 10 * PADN * 8  = 84480
//   scat :  9 * PADN * 4  = 38016
//   cnt  :  3 * NBIN * 4  = 12288
//   cinc :  3 * NBIN * 4  = 12288
//   hcol :  6 * NN  * 4   = 24576
//   ws   : 96 * 4         = 384
//   red  : 256 * 4        = 1024
#define SMEM_BYTES (10*PADN*8 + 9*PADN*4 + 3*NBIN*4 + 3*NBIN*4 + 6*NN*4 + 384 + 1024)

// ---- u32 inclusive block scan, 1 value/thread ----
__device__ __forceinline__ unsigned scanInclU32(unsigned v, unsigned* ws, int tid) {
    const int lane = tid & 31, wid = tid >> 5;
#pragma unroll
    for (int d = 1; d < 32; d <<= 1) {
        unsigned n = __shfl_up_sync(0xffffffffu, v, d);
        if (lane >= d) v += n;
    }
    if (lane == 31) ws[wid] = v;
    __syncthreads();
    if (wid == 0) {
        unsigned w = ws[lane];
#pragma unroll
        for (int d = 1; d < 32; d <<= 1) {
            unsigned n = __shfl_up_sync(0xffffffffu, w, d);
            if (lane >= d) w += n;
        }
        ws[lane] = w;
    }
    __syncthreads();
    if (wid > 0) v += ws[wid - 1];
    return v;
}

// ---- u32 inclusive block scan, 3 values/thread ----
__device__ __forceinline__ void scanInclU32x3(unsigned* v, unsigned* ws, int tid) {
    const int lane = tid & 31, wid = tid >> 5;
#pragma unroll
    for (int a = 0; a < 3; a++) {
#pragma unroll
        for (int d = 1; d < 32; d <<= 1) {
            unsigned n = __shfl_up_sync(0xffffffffu, v[a], d);
            if (lane >= d) v[a] += n;
        }
        if (lane == 31) ws[a * 32 + wid] = v[a];
    }
    __syncthreads();
    if (wid == 0) {
#pragma unroll
        for (int a = 0; a < 3; a++) {
            unsigned w = ws[a * 32 + lane];
#pragma unroll
            for (int d = 1; d < 32; d <<= 1) {
                unsigned n = __shfl_up_sync(0xffffffffu, w, d);
                if (lane >= d) w += n;
            }
            ws[a * 32 + lane] = w;
        }
    }
    __syncthreads();
    if (wid > 0) {
#pragma unroll
        for (int a = 0; a < 3; a++) v[a] += ws[a * 32 + wid - 1];
    }
}

// ---- block min/max of 1 float. red must hold 192 floats. ----
__device__ __forceinline__ float2 blockMinMax(float v, float* s, int tid) {
    const int lane = tid & 31, wid = tid >> 5;
    float mx = v, mn = v;
#pragma unroll
    for (int d = 16; d >= 1; d >>= 1) {
        mx = fmaxf(mx, __shfl_xor_sync(0xffffffffu, mx, d));
        mn = fminf(mn, __shfl_xor_sync(0xffffffffu, mn, d));
    }
    if (lane == 0) { s[wid] = mx; s[32 + wid] = mn; }
    __syncthreads();
    if (wid == 0) {
        mx = s[lane]; mn = s[32 + lane];
#pragma unroll
        for (int d = 16; d >= 1; d >>= 1) {
            mx = fmaxf(mx, __shfl_xor_sync(0xffffffffu, mx, d));
            mn = fminf(mn, __shfl_xor_sync(0xffffffffu, mn, d));
        }
        if (lane == 0) { s[0] = mx; s[32] = mn; }
    }
    __syncthreads();
    float2 r = make_float2(s[32], s[0]);   // (min, max)
    __syncthreads();
    return r;
}

// ---- block min/max of 3 floats at once ----
__device__ __forceinline__ void blockMinMax3(const float* sdv, float* mn3, float* mx3,
                                             float* s, int tid) {
    const int lane = tid & 31, wid = tid >> 5;
    float a0 = sdv[0], a1 = sdv[1], a2 = sdv[2];
    float b0 = a0, b1 = a1, b2 = a2;
#pragma unroll
    for (int d = 16; d >= 1; d >>= 1) {
        a0 = fmaxf(a0, __shfl_xor_sync(0xffffffffu, a0, d));
        a1 = fmaxf(a1, __shfl_xor_sync(0xffffffffu, a1, d));
        a2 = fmaxf(a2, __shfl_xor_sync(0xffffffffu, a2, d));
        b0 = fminf(b0, __shfl_xor_sync(0xffffffffu, b0, d));
        b1 = fminf(b1, __shfl_xor_sync(0xffffffffu, b1, d));
        b2 = fminf(b2, __shfl_xor_sync(0xffffffffu, b2, d));
    }
    if (lane == 0) {
        s[wid] = a0; s[32 + wid] = a1; s[64 + wid] = a2;
        s[96 + wid] = b0; s[128 + wid] = b1; s[160 + wid] = b2;
    }
    __syncthreads();
    if (wid == 0) {
        a0 = s[lane]; a1 = s[32 + lane]; a2 = s[64 + lane];
        b0 = s[96 + lane]; b1 = s[128 + lane]; b2 = s[160 + lane];
#pragma unroll
        for (int d = 16; d >= 1; d >>= 1) {
            a0 = fmaxf(a0, __shfl_xor_sync(0xffffffffu, a0, d));
            a1 = fmaxf(a1, __shfl_xor_sync(0xffffffffu, a1, d));
            a2 = fmaxf(a2, __shfl_xor_sync(0xffffffffu, a2, d));
            b0 = fminf(b0, __shfl_xor_sync(0xffffffffu, b0, d));
            b1 = fminf(b1, __shfl_xor_sync(0xffffffffu, b1, d));
            b2 = fminf(b2, __shfl_xor_sync(0xffffffffu, b2, d));
        }
        if (lane == 0) {
            s[0] = a0; s[32] = a1; s[64] = a2;
            s[96] = b0; s[128] = b1; s[160] = b2;
        }
    }
    __syncthreads();
    mx3[0] = s[0]; mx3[1] = s[32]; mx3[2] = s[64];
    mn3[0] = s[96]; mn3[1] = s[128]; mn3[2] = s[160];
    __syncthreads();
}

// ---- per-warp exact s64 inclusive prefix over 1024 scattered elements ----
// element value = Barr[id] (^5 if powA) * (usew ? wm[id] : 1)
__device__ __forceinline__ void warpScanArray(
    const float* __restrict__ Barr, const float* __restrict__ wm,
    bool usew, bool powA, long long* __restrict__ tabrow, int lane)
{
    const int base = lane * 32;
    long long acc = 0;
#pragma unroll 8
    for (int k = 0; k < 32; k++) {
        int id = IDX(base + k);
        float v = Barr[id];
        if (powA) { float b2 = v * v; v = b2 * b2 * v; }   // A = B^5 (exact same exp base)
        if (usew) v *= wm[id];
        acc += fpenc(v);
        tabrow[id] = acc;              // lane-local inclusive
    }
    long long tot = acc, s = acc;
#pragma unroll
    for (int d = 1; d < 32; d <<= 1) {
        long long n = __shfl_up_sync(0xffffffffu, s, d);
        if (lane >= d) s += n;
    }
    long long off = s - tot;           // exclusive lane offset
    if (off != 0) {
#pragma unroll 8
        for (int k = 0; k < 32; k++) {
            int id = IDX(base + k);
            tabrow[id] += off;
        }
    }
}

// ---------------------------------------------------------------------------
// Fused 2-layer GAT: one block per batch, 1024 threads.
// ---------------------------------------------------------------------------
__global__ void __launch_bounds__(1024, 1) gat_fused_kernel(
    const float* __restrict__ x,    // (B, N, 4)
    const float* __restrict__ W1,   // (3, 4, 2)
    const float* __restrict__ a1,   // (3, 4, 1)
    const float* __restrict__ W2,   // (1, 6, 4)
    const float* __restrict__ a2,   // (1, 8, 1)
    float* __restrict__ y)          // (B, N, 4)
{
    extern __shared__ unsigned char smraw[];
    long long (*tab)[PADN] = reinterpret_cast<long long(*)[PADN]>(smraw);
    float     (*scat)[PADN] = reinterpret_cast<float(*)[PADN]>(smraw + 10 * PADN * 8);
    unsigned* cnt  = reinterpret_cast<unsigned*>(smraw + 10 * PADN * 8 + 9 * PADN * 4);
    unsigned* cinc = cnt + 3 * NBIN;
    float* hcol = reinterpret_cast<float*>(cinc + 3 * NBIN);
    unsigned* ws = reinterpret_cast<unsigned*>(hcol + 6 * NN);
    float* red = reinterpret_cast<float*>(ws + 96);

    const int b = blockIdx.x;
    const int tid = threadIdx.x;
    const int lane = tid & 31, wid = tid >> 5;

    // zero all 3 count arrays (visible by blockMinMax3's internal barrier)
    cnt[tid] = 0u; cnt[NBIN + tid] = 0u; cnt[2 * NBIN + tid] = 0u;

    // ===================== LAYER 1 =====================
    float4 xv = reinterpret_cast<const float4*>(x)[b * NN + tid];
    float whv[3][2], ssv[3], sdv[3];
#pragma unroll
    for (int hd = 0; hd < 3; hd++) {
        const float* W = W1 + hd * 8;
        const float* A = a1 + hd * 4;
        float wh0 = xv.x * W[0] + xv.y * W[2] + xv.z * W[4] + xv.w * W[6];
        float wh1 = xv.x * W[1] + xv.y * W[3] + xv.z * W[5] + xv.w * W[7];
        whv[hd][0] = wh0; whv[hd][1] = wh1;
        ssv[hd] = wh0 * A[0] + wh1 * A[1];
        sdv[hd] = wh0 * A[2] + wh1 * A[3];
    }

    float mn3[3], mx3[3];
    blockMinMax3(sdv, mn3, mx3, red, tid);

    float scl[3]; int bj[3]; unsigned tick[3];
#pragma unroll
    for (int hd = 0; hd < 3; hd++) {
        float range = mx3[hd] - mn3[hd];
        scl[hd] = (range > 1e-30f) ? ((float)NBIN / range) : 0.0f;
        bj[hd] = min((int)((sdv[hd] - mn3[hd]) * scl[hd]), NBIN - 1);
        tick[hd] = atomicAdd(&cnt[hd * NBIN + bj[hd]], 1u);
    }
    __syncthreads();

    unsigned cv[3] = { cnt[tid], cnt[NBIN + tid], cnt[2 * NBIN + tid] };
    scanInclU32x3(cv, ws, tid);
    cinc[tid] = cv[0]; cinc[NBIN + tid] = cv[1]; cinc[2 * NBIN + tid] = cv[2];
    __syncthreads();

#pragma unroll
    for (int hd = 0; hd < 3; hd++) {
        int pos = (int)(cinc[hd * NBIN + bj[hd]] - cnt[hd * NBIN + bj[hd]] + tick[hd]);
        int ip = IDX(pos);
        scat[hd * 3 + 0][ip] = __expf(0.2f * (sdv[hd] - mx3[hd]));   // B; A = B^5
        scat[hd * 3 + 1][ip] = whv[hd][0];
        scat[hd * 3 + 2][ip] = whv[hd][1];
    }
    __syncthreads();

    // per-head: warp-parallel exact scans, then row phase -> hcol
    for (int hd = 0; hd < 3; hd++) {
        if (wid < 6) {
            int grp = wid / 3, c = wid % 3;
            warpScanArray(scat[hd * 3],
                          c ? scat[hd * 3 + c] : scat[hd * 3],
                          c != 0, grp == 1, tab[wid], lane);
        }
        __syncthreads();

        const float u = ssv[hd] + mx3[hd];
        const float m = fmaxf(u, 0.2f * u);
        const float p = __expf(u - m);
        const float q = __expf(0.2f * u - m);
        const float t = -ssv[hd];
        const int bt = (t < mn3[hd]) ? -1
                     : min((int)((t - mn3[hd]) * scl[hd]), NBIN - 1);
        const unsigned post = (bt >= 0) ? cinc[hd * NBIN + bt] : 0u;

        long long P0 = 0, P1 = 0, P2 = 0, P3 = 0, P4 = 0, P5 = 0;
        if (post > 0) {
            int iq = IDX((int)post - 1);
            P0 = tab[0][iq]; P1 = tab[1][iq]; P2 = tab[2][iq];
            P3 = tab[3][iq]; P4 = tab[4][iq]; P5 = tab[5][iq];
        }
        const int il = IDX(NN - 1);
        const long long T3 = tab[3][il], T4 = tab[4][il], T5 = tab[5][il];

        const float denom = q * fpdec(P0) + p * fpdec(T3 - P3);
        const float inv = 1.0f / denom;
        float o0 = (q * fpdec(P1) + p * fpdec(T4 - P4)) * inv;
        float o1 = (q * fpdec(P2) + p * fpdec(T5 - P5)) * inv;
        o0 = (o0 > 0.f) ? o0 : expm1f(o0);
        o1 = (o1 > 0.f) ? o1 : expm1f(o1);

        hcol[(2 * hd) * NN + tid] = o0;
        hcol[(2 * hd + 1) * NN + tid] = o1;
        __syncthreads();   // tab reuse by next head / layer 2
    }

    // ===================== LAYER 2 =====================
    cnt[tid] = 0u;   // reuse region 0 (barrier inside blockMinMax covers visibility)

    float xf[6];
#pragma unroll
    for (int c = 0; c < 6; c++) xf[c] = hcol[c * NN + tid];
    float wh2[4];
#pragma unroll
    for (int o = 0; o < 4; o++) {
        float acc = 0.f;
#pragma unroll
        for (int f = 0; f < 6; f++) acc = fmaf(xf[f], W2[f * 4 + o], acc);
        wh2[o] = acc;
    }
    float ss2 = 0.f, sd2 = 0.f;
#pragma unroll
    for (int o = 0; o < 4; o++) {
        ss2 = fmaf(wh2[o], a2[o], ss2);
        sd2 = fmaf(wh2[o], a2[4 + o], sd2);
    }

    float2 mm = blockMinMax(sd2, red, tid);
    const float mn2 = mm.x, M2 = mm.y;
    const float range2 = M2 - mn2;
    const float scl2 = (range2 > 1e-30f) ? ((float)NBIN / range2) : 0.0f;

    const int bj2 = min((int)((sd2 - mn2) * scl2), NBIN - 1);
    const unsigned tick2 = atomicAdd(&cnt[bj2], 1u);
    __syncthreads();

    const unsigned ci2 = scanInclU32(cnt[tid], ws, tid);
    cinc[tid] = ci2;
    __syncthreads();

    {
        int pos = (int)(cinc[bj2] - cnt[bj2] + tick2);
        int ip = IDX(pos);
        scat[0][ip] = __expf(0.2f * (sd2 - M2));   // B; A = B^5
        scat[1][ip] = wh2[0];
        scat[2][ip] = wh2[1];
        scat[3][ip] = wh2[2];
        scat[4][ip] = wh2[3];
    }
    __syncthreads();

    if (wid < 10) {
        int grp = wid / 5, c = wid % 5;
        warpScanArray(scat[0],
                      c ? scat[c] : scat[0],
                      c != 0, grp == 1, tab[wid], lane);
    }
    __syncthreads();

    const float u = ss2 + M2;
    const float m = fmaxf(u, 0.2f * u);
    const float p = __expf(u - m);
    const float q = __expf(0.2f * u - m);
    const float t = -ss2;
    const int bt = (t < mn2) ? -1 : min((int)((t - mn2) * scl2), NBIN - 1);
    const unsigned post = (bt >= 0) ? cinc[bt] : 0u;

    long long P[10];
#pragma unroll
    for (int a = 0; a < 10; a++) P[a] = 0;
    if (post > 0) {
        int iq = IDX((int)post - 1);
#pragma unroll
        for (int a = 0; a < 10; a++) P[a] = tab[a][iq];
    }
    const int il = IDX(NN - 1);
    long long T[5];
#pragma unroll
    for (int a = 0; a < 5; a++) T[a] = tab[5 + a][il];

    const float denom = q * fpdec(P[0]) + p * fpdec(T[0] - P[5]);
    const float inv = 1.0f / denom;
    float o0 = (q * fpdec(P[1]) + p * fpdec(T[1] - P[6])) * inv;
    float o1 = (q * fpdec(P[2]) + p * fpdec(T[2] - P[7])) * inv;
    float o2 = (q * fpdec(P[3]) + p * fpdec(T[3] - P[8])) * inv;
    float o3 = (q * fpdec(P[4]) + p * fpdec(T[4] - P[9])) * inv;
    o0 = (o0 > 0.f) ? o0 : expm1f(o0);
    o1 = (o1 > 0.f) ? o1 : expm1f(o1);
    o2 = (o2 > 0.f) ? o2 : expm1f(o2);
    o3 = (o3 > 0.f) ? o3 : expm1f(o3);

    reinterpret_cast<float4*>(y)[b * NN + tid] = make_float4(o0, o1, o2, o3);
}

extern "C" void kernel_launch(void* const* d_in, const int* in_sizes, int n_in,
                              void* d_out, int out_size)
{
    const float* x  = (const float*)d_in[0];
    const float* W1 = (const float*)d_in[1];
    const float* a1 = (const float*)d_in[2];
    const float* W2 = (const float*)d_in[3];
    const float* a2 = (const float*)d_in[4];
    float* y = (float*)d_out;

    static int configured = 0;
    if (!configured) {
        cudaFuncSetAttribute(gat_fused_kernel,
                             cudaFuncAttributeMaxDynamicSharedMemorySize, SMEM_BYTES);
        configured = 1;
    }

    gat_fused_kernel<<<BB, 1024, SMEM_BYTES>>>(x, W1, a1, W2, a2, y);
}

// round 7
// speedup vs baseline: 1.4804x; 1.4804x over previous
#include <cuda_runtime.h>

#define NN   1024
#define BB   32
#define NBIN 1024

#define FPSCALE   0x1p40f
#define FPISCALE  0x1p-40f

__device__ float    g_h[BB * NN * 6];      // layer-1 output (B, N, 6)
__device__ unsigned g_ready[BB];           // producer->consumer flags (zero-init; consumers reset)

__device__ __forceinline__ long long fpenc(float v) { return (long long)(v * FPSCALE); }
__device__ __forceinline__ float     fpdec(long long u) { return __ll2float_rn(u) * FPISCALE; }

__device__ __forceinline__ int IDX(int i) { return i + (i >> 5); }
#define PADN (NN + (NN >> 5))   // 1056

// shared layout (bytes):
//   tab  : 10 * PADN * 8 = 84480
//   scat :  5 * PADN * 4 = 21120
//   cnt  : NBIN * 4      = 4096
//   cinc : NBIN * 4      = 4096
//   ws   : 32 * 4        = 128
//   red  : 256 * 4       = 1024
#define SMEM_BYTES (10*PADN*8 + 5*PADN*4 + 4096 + 4096 + 128 + 1024)

// ---- u32 inclusive block scan, 1 value/thread ----
__device__ __forceinline__ unsigned scanInclU32(unsigned v, unsigned* ws, int tid) {
    const int lane = tid & 31, wid = tid >> 5;
#pragma unroll
    for (int d = 1; d < 32; d <<= 1) {
        unsigned n = __shfl_up_sync(0xffffffffu, v, d);
        if (lane >= d) v += n;
    }
    if (lane == 31) ws[wid] = v;
    __syncthreads();
    if (wid == 0) {
        unsigned w = ws[lane];
#pragma unroll
        for (int d = 1; d < 32; d <<= 1) {
            unsigned n = __shfl_up_sync(0xffffffffu, w, d);
            if (lane >= d) w += n;
        }
        ws[lane] = w;
    }
    __syncthreads();
    if (wid > 0) v += ws[wid - 1];
    return v;
}

// ---- block min/max of 1 float. s must hold 64 floats. ----
__device__ __forceinline__ float2 blockMinMax(float v, float* s, int tid) {
    const int lane = tid & 31, wid = tid >> 5;
    float mx = v, mn = v;
#pragma unroll
    for (int d = 16; d >= 1; d >>= 1) {
        mx = fmaxf(mx, __shfl_xor_sync(0xffffffffu, mx, d));
        mn = fminf(mn, __shfl_xor_sync(0xffffffffu, mn, d));
    }
    if (lane == 0) { s[wid] = mx; s[32 + wid] = mn; }
    __syncthreads();
    if (wid == 0) {
        mx = s[lane]; mn = s[32 + lane];
#pragma unroll
        for (int d = 16; d >= 1; d >>= 1) {
            mx = fmaxf(mx, __shfl_xor_sync(0xffffffffu, mx, d));
            mn = fminf(mn, __shfl_xor_sync(0xffffffffu, mn, d));
        }
        if (lane == 0) { s[0] = mx; s[32] = mn; }
    }
    __syncthreads();
    float2 r = make_float2(s[32], s[0]);   // (min, max)
    __syncthreads();
    return r;
}

// ---- per-warp exact s64 inclusive prefix over 1024 scattered elements ----
// element value = Barr[id] (^5 if powA) * (usew ? wm[id] : 1)
__device__ __forceinline__ void warpScanArray(
    const float* __restrict__ Barr, const float* __restrict__ wm,
    bool usew, bool powA, long long* __restrict__ tabrow, int lane)
{
    const int base = lane * 32;
    long long acc = 0;
#pragma unroll 8
    for (int k = 0; k < 32; k++) {
        int id = IDX(base + k);
        float v = Barr[id];
        if (powA) { float b2 = v * v; v = b2 * b2 * v; }   // A = B^5
        if (usew) v *= wm[id];
        acc += fpenc(v);
        tabrow[id] = acc;              // lane-local inclusive
    }
    long long tot = acc, s = acc;
#pragma unroll
    for (int d = 1; d < 32; d <<= 1) {
        long long n = __shfl_up_sync(0xffffffffu, s, d);
        if (lane >= d) s += n;
    }
    long long off = s - tot;           // exclusive lane offset
    if (off != 0) {
#pragma unroll 8
        for (int k = 0; k < 32; k++) {
            int id = IDX(base + k);
            tabrow[id] += off;
        }
    }
}

// ---------------------------------------------------------------------------
// One kernel, 128 blocks: blocks 0..95 = layer-1 (head,batch) producers,
// blocks 96..127 = layer-2 per-batch consumers (spin on g_ready[b]).
// ---------------------------------------------------------------------------
__global__ void __launch_bounds__(1024, 1) gat_pc_kernel(
    const float* __restrict__ x,    // (B, N, 4)
    const float* __restrict__ W1,   // (3, 4, 2)
    const float* __restrict__ a1,   // (3, 4, 1)
    const float* __restrict__ W2,   // (1, 6, 4)
    const float* __restrict__ a2,   // (1, 8, 1)
    float* __restrict__ y)          // (B, N, 4)
{
    extern __shared__ unsigned char smraw[];
    long long (*tab)[PADN]  = reinterpret_cast<long long(*)[PADN]>(smraw);
    float     (*scat)[PADN] = reinterpret_cast<float(*)[PADN]>(smraw + 10 * PADN * 8);
    unsigned* cnt  = reinterpret_cast<unsigned*>(smraw + 10 * PADN * 8 + 5 * PADN * 4);
    unsigned* cinc = cnt + NBIN;
    unsigned* ws   = cinc + NBIN;
    float*    red  = reinterpret_cast<float*>(ws + 32);

    const int bid  = blockIdx.x;
    const int tid  = threadIdx.x;
    const int lane = tid & 31, wid = tid >> 5;

    cnt[tid] = 0u;

    if (bid < 96) {
        // ===================== LAYER 1 producer: (head, batch) =====================
        const int b  = bid / 3;
        const int hd = bid % 3;

        float w[8];
#pragma unroll
        for (int i = 0; i < 8; i++) w[i] = W1[hd * 8 + i];
        const float as0 = a1[hd * 4 + 0], as1 = a1[hd * 4 + 1];
        const float ad0 = a1[hd * 4 + 2], ad1 = a1[hd * 4 + 3];

        float4 xv = reinterpret_cast<const float4*>(x)[b * NN + tid];
        const float wh0 = xv.x * w[0] + xv.y * w[2] + xv.z * w[4] + xv.w * w[6];
        const float wh1 = xv.x * w[1] + xv.y * w[3] + xv.z * w[5] + xv.w * w[7];
        const float ss  = wh0 * as0 + wh1 * as1;
        const float sd  = wh0 * ad0 + wh1 * ad1;

        float2 mm = blockMinMax(sd, red, tid);   // internal barriers cover cnt zeroing
        const float mn = mm.x, M = mm.y;
        const float range = M - mn;
        const float scale = (range > 1e-30f) ? ((float)NBIN / range) : 0.0f;

        const int bj = min((int)((sd - mn) * scale), NBIN - 1);
        const unsigned ticket = atomicAdd(&cnt[bj], 1u);
        __syncthreads();

        cinc[tid] = scanInclU32(cnt[tid], ws, tid);
        __syncthreads();

        const int ip = IDX((int)(cinc[bj] - cnt[bj] + ticket));
        scat[0][ip] = __expf(0.2f * (sd - M));   // B; A = B^5
        scat[1][ip] = wh0;
        scat[2][ip] = wh1;
        __syncthreads();

        if (wid < 6) {
            int grp = wid / 3, c = wid % 3;
            warpScanArray(scat[0], c ? scat[c] : scat[0], c != 0, grp == 1,
                          tab[wid], lane);
        }
        __syncthreads();

        const float u = ss + M;
        const float m = fmaxf(u, 0.2f * u);
        const float p = __expf(u - m);
        const float q = __expf(0.2f * u - m);
        const float t = -ss;
        const int bt = (t < mn) ? -1 : min((int)((t - mn) * scale), NBIN - 1);
        const unsigned post = (bt >= 0) ? cinc[bt] : 0u;

        long long P0 = 0, P1 = 0, P2 = 0, P3 = 0, P4 = 0, P5 = 0;
        if (post > 0) {
            int iq = IDX((int)post - 1);
            P0 = tab[0][iq]; P1 = tab[1][iq]; P2 = tab[2][iq];
            P3 = tab[3][iq]; P4 = tab[4][iq]; P5 = tab[5][iq];
        }
        const int il = IDX(NN - 1);
        const long long T3 = tab[3][il], T4 = tab[4][il], T5 = tab[5][il];

        const float denom = q * fpdec(P0) + p * fpdec(T3 - P3);
        const float inv = 1.0f / denom;
        float o0 = (q * fpdec(P1) + p * fpdec(T4 - P4)) * inv;
        float o1 = (q * fpdec(P2) + p * fpdec(T5 - P5)) * inv;
        o0 = (o0 > 0.f) ? o0 : expm1f(o0);
        o1 = (o1 > 0.f) ? o1 : expm1f(o1);

        float* dst = g_h + (size_t)(b * NN + tid) * 6 + hd * 2;
        dst[0] = o0;
        dst[1] = o1;

        __threadfence();                 // each thread publishes its own stores
        __syncthreads();                 // all threads fenced before signal
        if (tid == 0) atomicAdd(&g_ready[b], 1u);

    } else {
        // ===================== LAYER 2 consumer: batch b =====================
        const int b = bid - 96;

        float w[24];
#pragma unroll
        for (int i = 0; i < 24; i++) w[i] = W2[i];
        float asv[4], adv[4];
#pragma unroll
        for (int o = 0; o < 4; o++) { asv[o] = a2[o]; adv[o] = a2[4 + o]; }

        if (tid == 0) {
            while (atomicAdd(&g_ready[b], 0u) < 3u) __nanosleep(64);
            __threadfence();             // acquire: order flag before data reads
        }
        __syncthreads();

        const float* hb = g_h + (size_t)(b * NN + tid) * 6;
        float2 h0 = *reinterpret_cast<const float2*>(hb);
        float2 h1 = *reinterpret_cast<const float2*>(hb + 2);
        float2 h2 = *reinterpret_cast<const float2*>(hb + 4);
        float xf[6] = {h0.x, h0.y, h1.x, h1.y, h2.x, h2.y};
        float wh[4];
#pragma unroll
        for (int o = 0; o < 4; o++) {
            float acc = 0.f;
#pragma unroll
            for (int f = 0; f < 6; f++) acc = fmaf(xf[f], w[f * 4 + o], acc);
            wh[o] = acc;
        }
        float ss = 0.f, sd = 0.f;
#pragma unroll
        for (int o = 0; o < 4; o++) {
            ss = fmaf(wh[o], asv[o], ss);
            sd = fmaf(wh[o], adv[o], sd);
        }

        float2 mm = blockMinMax(sd, red, tid);   // barrier: all g_h reads done
        if (tid == 0) atomicExch(&g_ready[b], 0u);   // reset for next replay
        const float mn = mm.x, M = mm.y;
        const float range = M - mn;
        const float scale = (range > 1e-30f) ? ((float)NBIN / range) : 0.0f;

        const int bj = min((int)((sd - mn) * scale), NBIN - 1);
        const unsigned ticket = atomicAdd(&cnt[bj], 1u);
        __syncthreads();

        cinc[tid] = scanInclU32(cnt[tid], ws, tid);
        __syncthreads();

        const int ip = IDX((int)(cinc[bj] - cnt[bj] + ticket));
        scat[0][ip] = __expf(0.2f * (sd - M));   // B; A = B^5
        scat[1][ip] = wh[0];
        scat[2][ip] = wh[1];
        scat[3][ip] = wh[2];
        scat[4][ip] = wh[3];
        __syncthreads();

        if (wid < 10) {
            int grp = wid / 5, c = wid % 5;
            warpScanArray(scat[0], c ? scat[c] : scat[0], c != 0, grp == 1,
                          tab[wid], lane);
        }
        __syncthreads();

        const float u = ss + M;
        const float m = fmaxf(u, 0.2f * u);
        const float p = __expf(u - m);
        const float q = __expf(0.2f * u - m);
        const float t = -ss;
        const int bt = (t < mn) ? -1 : min((int)((t - mn) * scale), NBIN - 1);
        const unsigned post = (bt >= 0) ? cinc[bt] : 0u;

        long long P[10];
#pragma unroll
        for (int a = 0; a < 10; a++) P[a] = 0;
        if (post > 0) {
            int iq = IDX((int)post - 1);
#pragma unroll
            for (int a = 0; a < 10; a++) P[a] = tab[a][iq];
        }
        const int il = IDX(NN - 1);
        long long T[5];
#pragma unroll
        for (int a = 0; a < 5; a++) T[a] = tab[5 + a][il];

        const float denom = q * fpdec(P[0]) + p * fpdec(T[0] - P[5]);
        const float inv = 1.0f / denom;
        float o0 = (q * fpdec(P[1]) + p * fpdec(T[1] - P[6])) * inv;
        float o1 = (q * fpdec(P[2]) + p * fpdec(T[2] - P[7])) * inv;
        float o2 = (q * fpdec(P[3]) + p * fpdec(T[3] - P[8])) * inv;
        float o3 = (q * fpdec(P[4]) + p * fpdec(T[4] - P[9])) * inv;
        o0 = (o0 > 0.f) ? o0 : expm1f(o0);
        o1 = (o1 > 0.f) ? o1 : expm1f(o1);
        o2 = (o2 > 0.f) ? o2 : expm1f(o2);
        o3 = (o3 > 0.f) ? o3 : expm1f(o3);

        reinterpret_cast<float4*>(y)[b * NN + tid] = make_float4(o0, o1, o2, o3);
    }
}

extern "C" void kernel_launch(void* const* d_in, const int* in_sizes, int n_in,
                              void* d_out, int out_size)
{
    const float* x  = (const float*)d_in[0];
    const float* W1 = (const float*)d_in[1];
    const float* a1 = (const float*)d_in[2];
    const float* W2 = (const float*)d_in[3];
    const float* a2 = (const float*)d_in[4];
    float* y = (float*)d_out;

    static int configured = 0;
    if (!configured) {
        cudaFuncSetAttribute(gat_pc_kernel,
                             cudaFuncAttributeMaxDynamicSharedMemorySize, SMEM_BYTES);
        configured = 1;
    }

    gat_pc_kernel<<<96 + BB, 1024, SMEM_BYTES>>>(x, W1, a1, W2, a2, y);
}